// round 16
// baseline (speedup 1.0000x reference)
#include <cuda_runtime.h>
#include <cstdint>

#define BATCH 4
#define SEQ   4096
#define DIM   1024
#define MTOT  (BATCH * SEQ)      // 16384

#define BM 128
#define BN 128
#define BK 32
#define NTHR 256
#define TILE_FLOATS (BM * BK)     // 4096 floats = 16384 B (swizzled, no pad)
#define TILE_BYTES  (TILE_FLOATS * 4)
#define NSTAGE 3
#define SMEM_DYN (NSTAGE * 2 * TILE_BYTES)   // 98304 B -> 2 CTA/SM = 192KB

// Scratch (allocation-free rule: __device__ globals)
__device__ float g_Q[(size_t)MTOT * DIM];
__device__ float g_K[(size_t)MTOT * DIM];
__device__ float g_V[(size_t)MTOT * DIM];          // holds V^T: [DIM][MTOT]
__device__ float g_S[(size_t)BATCH * SEQ * SEQ];
__device__ float g_X[(size_t)MTOT * DIM];          // tf32-rounded x
__device__ float g_W[(size_t)3 * DIM * DIM];       // tf32-rounded [Wq;Wk;Wv]

// ---------------------------------------------------------------------------
static __device__ __forceinline__ uint32_t s2u(const void* p) {
    uint32_t a;
    asm("{ .reg .u64 t; cvta.to.shared.u64 t, %1; cvt.u32.u64 %0, t; }"
        : "=r"(a) : "l"(p));
    return a;
}
static __device__ __forceinline__ uint32_t f2tf32(float f) {
    uint32_t r;
    asm("cvt.rna.tf32.f32 %0, %1;" : "=r"(r) : "f"(f));
    return r;
}
static __device__ __forceinline__ float rtf(float f) {
    return __uint_as_float(f2tf32(f));
}
static __device__ __forceinline__ void cpasync16(uint32_t saddr, const void* gaddr) {
    asm volatile("cp.async.cg.shared.global [%0], [%1], 16;"
                 :: "r"(saddr), "l"(gaddr) : "memory");
}
static __device__ __forceinline__ void cpcommit() {
    asm volatile("cp.async.commit_group;" ::: "memory");
}
static __device__ __forceinline__ void cpwait0() {
    asm volatile("cp.async.wait_group 0;" ::: "memory");
}
static __device__ __forceinline__ void cpwait1() {
    asm volatile("cp.async.wait_group 1;" ::: "memory");
}
static __device__ __forceinline__ void mma_tf32(float* c, uint32_t a0, uint32_t a1,
                                                uint32_t a2, uint32_t a3,
                                                uint32_t b0, uint32_t b1) {
    asm volatile(
        "mma.sync.aligned.m16n8k8.row.col.f32.tf32.tf32.f32 "
        "{%0,%1,%2,%3}, {%4,%5,%6,%7}, {%8,%9}, {%0,%1,%2,%3};"
        : "+f"(c[0]), "+f"(c[1]), "+f"(c[2]), "+f"(c[3])
        : "r"(a0), "r"(a1), "r"(a2), "r"(a3), "r"(b0), "r"(b1));
}
// Row-swizzle function for 16B chunks within a 128B row.
static __device__ __forceinline__ int swzf(int r) {
    return 2 * (r & 3) + ((r >> 2) & 1);
}

// ---------------------------------------------------------------------------
// Pre-round x to tf32 (rna), float4 granularity.
// ---------------------------------------------------------------------------
__global__ void __launch_bounds__(256)
round_tf32(const float4* __restrict__ in, float4* __restrict__ out, int n4)
{
    int i = blockIdx.x * 256 + threadIdx.x;
    if (i < n4) {
        float4 v = in[i];
        out[i] = make_float4(rtf(v.x), rtf(v.y), rtf(v.z), rtf(v.w));
    }
}

// Round the 3 weight matrices into concatenated g_W in one launch.
__global__ void __launch_bounds__(256)
round_w3(const float4* __restrict__ wq, const float4* __restrict__ wk,
         const float4* __restrict__ wv, float4* __restrict__ out, int n4)
{
    int i = blockIdx.x * 256 + threadIdx.x;
    if (i >= n4) return;
    const float4* src = (blockIdx.y == 0) ? wq : (blockIdx.y == 1) ? wk : wv;
    float4 v = src[i];
    out[(size_t)blockIdx.y * n4 + i] =
        make_float4(rtf(v.x), rtf(v.y), rtf(v.z), rtf(v.w));
}

// ---------------------------------------------------------------------------
// tf32 mma.sync NT GEMM: C[m][n] = alpha * sum_k A[m][k] * B[n][k]
// All shape parameters are compile-time template constants so address math
// folds to immediates and ptxas gets register headroom to pipeline fragment
// loads. 3-stage cp.async pipeline, one __syncthreads per K-chunk, XOR
// swizzle (j ^= f(row), f(r)=2(r&3)+((r>>2)&1)), LDS.64 fragments with the
// shared k-pair bijection {t4,t4+4}->{2t4,2t4+1}. Bit-identical results.
// FLAGS: 1 = causal tile skip + diagonal warp-skip, 2 = transposed epilogue,
//        4 = causal K bound, 8 = round output, 16 = fused-QKV routing,
//        32 = reversed m-tile order (LPT)
// ---------------------------------------------------------------------------
template<int KK, int LDA, int LDB, int LDC, long SA, long SB, long SC, int FLAGS>
__global__ void __launch_bounds__(NTHR, 2)
gemm_mma(const float* __restrict__ A, const float* __restrict__ B,
         float* __restrict__ C, float* __restrict__ C2, float* __restrict__ C3,
         float alpha)
{
    const int my = (FLAGS & 32) ? (gridDim.y - 1 - blockIdx.y) : blockIdx.y;
    const int m0 = my * BM;
    const int n0 = blockIdx.x * BN;          // B-space n origin
    if ((FLAGS & 1) && n0 > m0) return;

    A += (long)blockIdx.z * SA;
    B += (long)blockIdx.z * SB;

    extern __shared__ float smf[];
    const uint32_t sa = s2u(smf);

    const int tid  = threadIdx.x;
    const int lane = tid & 31;
    const int w    = tid >> 5;
    const int wm   = (w >> 2) * 64;     // warp tile M origin (0 or 64)
    const int wn   = (w & 3) * 32;      // warp tile N origin (0..96)
    const int g    = lane >> 2;         // 0..7
    const int t4   = lane & 3;          // 0..3

    // Diagonal warp-skip: on n0==m0 causal tiles, warps whose entire 64x32
    // warp tile is strictly above the diagonal produce values softmax
    // overwrites/ignores. They skip fragment loads + MMAs (still copy+sync).
    const bool do_mma = !((FLAGS & 1) && n0 == m0 && wn >= wm + 64);

    const int kend = (FLAGS & 4) ? min(KK, m0 + BM) : KK;
    const int nc   = kend / BK;

    // Global->smem geometry: 4 x 16B cp.async per thread per operand per chunk
    const int lr  = tid >> 3;           // 0..31 base row
    const int lc4 = (tid & 7) * 4;      // float col 0,4,...,28 (nominal chunk)
    const int jw  = (tid & 7) ^ swzf(lr);   // swizzled write chunk (same all i)
    const float* Ag[4]; const float* Bg[4];
    uint32_t sob[4];                    // swizzled smem byte offset in a tile
    #pragma unroll
    for (int i = 0; i < 4; i++) {
        const int row = lr + 32 * i;
        Ag[i] = A + (long)(m0 + row) * LDA + lc4;
        Bg[i] = B + (long)(n0 + row) * LDB + lc4;
        sob[i] = (uint32_t)(row * 128 + jw * 16);
    }

    // Fragment read constants (floats): row base + cb + kofs[ks]
    const int fg = swzf(g);
    const int cb = 4 * ((t4 >> 1) ^ (fg & 1)) + 2 * (t4 & 1);
    const int fh = fg >> 1;

    float acc[4][4][4];
    #pragma unroll
    for (int i = 0; i < 4; i++)
        #pragma unroll
        for (int j = 0; j < 4; j++)
            #pragma unroll
            for (int k = 0; k < 4; k++) acc[i][j][k] = 0.f;

    // prologue: chunk 0 -> stage 0, chunk 1 -> stage 1
    {
        #pragma unroll
        for (int i = 0; i < 4; i++) {
            cpasync16(sa + sob[i], Ag[i]);
            cpasync16(sa + TILE_BYTES + sob[i], Bg[i]);
            Ag[i] += BK; Bg[i] += BK;
        }
        cpcommit();
    }
    if (nc > 1) {
        const uint32_t st = 2u * TILE_BYTES;
        #pragma unroll
        for (int i = 0; i < 4; i++) {
            cpasync16(sa + st + sob[i], Ag[i]);
            cpasync16(sa + st + TILE_BYTES + sob[i], Bg[i]);
            Ag[i] += BK; Bg[i] += BK;
        }
        cpcommit();
    }

    int stage = 0;            // stage holding chunk c
    int wstage = 2;           // stage receiving chunk c+2
    for (int c = 0; c < nc; c++) {
        if (c + 1 < nc) cpwait1(); else cpwait0();   // group c complete
        __syncthreads();      // data visible; stage 'wstage' fully consumed

        if (c + 2 < nc) {
            const uint32_t st = (uint32_t)wstage * 2u * TILE_BYTES;
            #pragma unroll
            for (int i = 0; i < 4; i++) {
                cpasync16(sa + st + sob[i], Ag[i]);
                cpasync16(sa + st + TILE_BYTES + sob[i], Bg[i]);
                Ag[i] += BK; Bg[i] += BK;
            }
            cpcommit();
        }

        if (do_mma) {
            const float* Au = smf + stage * 2 * TILE_FLOATS;
            const float* Bu = Au + TILE_FLOATS;
            #pragma unroll
            for (int ks = 0; ks < 4; ks++) {
                const int kf = 8 * (ks ^ fh) + cb;   // swizzled k-offset
                uint32_t af[4][4];
                #pragma unroll
                for (int tm = 0; tm < 4; tm++) {
                    const float* ar = Au + (wm + tm * 16 + g) * 32 + kf;
                    uint2 lo = *(const uint2*)ar;
                    uint2 hi = *(const uint2*)(ar + 256);   // +8 rows
                    af[tm][0] = lo.x; af[tm][2] = lo.y;     // k=2t4, 2t4+1
                    af[tm][1] = hi.x; af[tm][3] = hi.y;
                }
                uint32_t bf[4][2];
                #pragma unroll
                for (int tn = 0; tn < 4; tn++) {
                    uint2 bv = *(const uint2*)(Bu + (wn + tn * 8 + g) * 32 + kf);
                    bf[tn][0] = bv.x; bf[tn][1] = bv.y;
                }
                #pragma unroll
                for (int tm = 0; tm < 4; tm++)
                    #pragma unroll
                    for (int tn = 0; tn < 4; tn++)
                        mma_tf32(acc[tm][tn], af[tm][0], af[tm][1], af[tm][2],
                                 af[tm][3], bf[tn][0], bf[tn][1]);
            }
        }

        stage  = (stage == NSTAGE - 1) ? 0 : stage + 1;
        wstage = (wstage == NSTAGE - 1) ? 0 : wstage + 1;
    }

    // Output routing
    float* Cc = C;
    int  nc0  = n0;
    int  ldcc = LDC;
    bool trans = (FLAGS & 2) != 0;
    if (FLAGS & 16) {
        const int ci = blockIdx.x >> 3;
        nc0 = (blockIdx.x & 7) * BN;
        if (ci == 1)      Cc = C2;
        else if (ci == 2) { Cc = C3; trans = true; ldcc = MTOT; }
    }
    Cc += (long)blockIdx.z * SC;

    const bool rnd = (FLAGS & 8) != 0;
    if (trans) {
        #pragma unroll
        for (int tm = 0; tm < 4; tm++) {
            const int mA = m0 + wm + tm * 16 + g;
            #pragma unroll
            for (int tn = 0; tn < 4; tn++) {
                const int n = nc0 + wn + tn * 8 + t4 * 2;
                float v0 = alpha * acc[tm][tn][0], v1 = alpha * acc[tm][tn][1];
                float v2 = alpha * acc[tm][tn][2], v3 = alpha * acc[tm][tn][3];
                if (rnd) { v0 = rtf(v0); v1 = rtf(v1); v2 = rtf(v2); v3 = rtf(v3); }
                Cc[(long)n * ldcc + mA]           = v0;
                Cc[(long)(n + 1) * ldcc + mA]     = v1;
                Cc[(long)n * ldcc + mA + 8]       = v2;
                Cc[(long)(n + 1) * ldcc + mA + 8] = v3;
            }
        }
    } else {
        #pragma unroll
        for (int tm = 0; tm < 4; tm++) {
            const int mA = m0 + wm + tm * 16 + g;
            #pragma unroll
            for (int tn = 0; tn < 4; tn++) {
                const int n = nc0 + wn + tn * 8 + t4 * 2;
                float v0 = alpha * acc[tm][tn][0], v1 = alpha * acc[tm][tn][1];
                float v2 = alpha * acc[tm][tn][2], v3 = alpha * acc[tm][tn][3];
                if (rnd) { v0 = rtf(v0); v1 = rtf(v1); v2 = rtf(v2); v3 = rtf(v3); }
                *(float2*)(Cc + (long)mA * ldcc + n)       = make_float2(v0, v1);
                *(float2*)(Cc + (long)(mA + 8) * ldcc + n) = make_float2(v2, v3);
            }
        }
    }
}

// ---------------------------------------------------------------------------
// Causal row softmax, in place. float4 traffic + shuffle reductions.
// Writes tf32-rounded P and zero-fills (q, 128-tile boundary).
// ---------------------------------------------------------------------------
__global__ void __launch_bounds__(256)
softmax_causal(float* __restrict__ S_, int S)
{
    const long row = blockIdx.x;            // b*S + q
    const int  q   = (int)(row & (long)(S - 1));
    float* p = S_ + row * (long)S;
    const int n = q + 1;
    const int n4 = n >> 2;                  // full float4s
    const int nr = n & 3;                   // tail elements

    __shared__ float buf[SEQ];
    __shared__ float red[8];
    float4* const p4   = (float4*)p;
    float4* const buf4 = (float4*)buf;
    const int tid  = threadIdx.x;
    const int lane = tid & 31;
    const int wid  = tid >> 5;

    // pass 1: load + max
    float lmax = -3.4e38f;
    for (int i = tid; i < n4; i += 256) {
        float4 v = p4[i];
        buf4[i] = v;
        lmax = fmaxf(fmaxf(lmax, fmaxf(v.x, v.y)), fmaxf(v.z, v.w));
    }
    if (tid < nr) {
        float v = p[n4 * 4 + tid];
        buf[n4 * 4 + tid] = v;
        lmax = fmaxf(lmax, v);
    }
    #pragma unroll
    for (int s = 16; s > 0; s >>= 1)
        lmax = fmaxf(lmax, __shfl_xor_sync(0xffffffffu, lmax, s));
    if (lane == 0) red[wid] = lmax;
    __syncthreads();
    float m = red[0];
    #pragma unroll
    for (int i = 1; i < 8; i++) m = fmaxf(m, red[i]);
    __syncthreads();

    // pass 2: exp + sum (in smem)
    float lsum = 0.f;
    for (int i = tid; i < n4; i += 256) {
        float4 v = buf4[i];
        v.x = __expf(v.x - m); v.y = __expf(v.y - m);
        v.z = __expf(v.z - m); v.w = __expf(v.w - m);
        buf4[i] = v;
        lsum += (v.x + v.y) + (v.z + v.w);
    }
    if (tid < nr) {
        float e = __expf(buf[n4 * 4 + tid] - m);
        buf[n4 * 4 + tid] = e;
        lsum += e;
    }
    #pragma unroll
    for (int s = 16; s > 0; s >>= 1)
        lsum += __shfl_xor_sync(0xffffffffu, lsum, s);
    if (lane == 0) red[wid] = lsum;
    __syncthreads();
    float tot = 0.f;
    #pragma unroll
    for (int i = 0; i < 8; i++) tot += red[i];
    const float inv = 1.0f / tot;

    // pass 3: normalize + tf32-round + store; zero-fill to tile boundary
    for (int i = tid; i < n4; i += 256) {
        float4 v = buf4[i];
        p4[i] = make_float4(rtf(v.x * inv), rtf(v.y * inv),
                            rtf(v.z * inv), rtf(v.w * inv));
    }
    if (tid < nr) p[n4 * 4 + tid] = rtf(buf[n4 * 4 + tid] * inv);
    const int zend = ((q >> 7) + 1) << 7;   // next multiple of BM=128
    for (int i = n + tid; i < zend; i += 256) p[i] = 0.f;
}

// ---------------------------------------------------------------------------
extern "C" void kernel_launch(void* const* d_in, const int* in_sizes, int n_in,
                              void* d_out, int out_size)
{
    const float* x  = (const float*)d_in[0];
    const float* Wq = (const float*)d_in[1];
    const float* Wk = (const float*)d_in[2];
    const float* Wv = (const float*)d_in[3];
    float* out = (float*)d_out;

    float *Q, *Kd, *Vt, *Sc, *Xr, *Wc;
    cudaGetSymbolAddress((void**)&Q,  g_Q);
    cudaGetSymbolAddress((void**)&Kd, g_K);
    cudaGetSymbolAddress((void**)&Vt, g_V);
    cudaGetSymbolAddress((void**)&Sc, g_S);
    cudaGetSymbolAddress((void**)&Xr, g_X);
    cudaGetSymbolAddress((void**)&Wc, g_W);

    constexpr long sQK = (long)SEQ * DIM;
    constexpr long sSS = (long)SEQ * SEQ;

    // Template instantiations
    auto kQKV = gemm_mma<DIM, DIM, DIM, DIM, 0L, 0L, 0L, 8 | 16>;
    auto kSco = gemm_mma<DIM, DIM, DIM, SEQ, sQK, sQK, sSS, 1>;
    auto kPV  = gemm_mma<SEQ, SEQ, MTOT, DIM, sSS, (long)SEQ, sQK, 4 | 32>;
    cudaFuncSetAttribute(kQKV, cudaFuncAttributeMaxDynamicSharedMemorySize,
                         SMEM_DYN);
    cudaFuncSetAttribute(kSco, cudaFuncAttributeMaxDynamicSharedMemorySize,
                         SMEM_DYN);
    cudaFuncSetAttribute(kPV,  cudaFuncAttributeMaxDynamicSharedMemorySize,
                         SMEM_DYN);

    // tf32-round inputs; weights concatenated into g_W = [Wq;Wk;Wv]
    const int nx4 = (MTOT * DIM) / 4, nw4 = (DIM * DIM) / 4;
    round_tf32<<<(nx4 + 255) / 256, 256>>>((const float4*)x, (float4*)Xr, nx4);
    {
        dim3 gW((nw4 + 255) / 256, 3, 1);
        round_w3<<<gW, 256>>>((const float4*)Wq, (const float4*)Wk,
                              (const float4*)Wv, (float4*)Wc, nw4);
    }

    // Fused QKV projection: N = 3072 over concatenated weights.
    // n-tiles 0-7 -> Q, 8-15 -> K, 16-23 -> V^T (transposed, ldc=MTOT)
    dim3 gP(3 * DIM / BN, MTOT / BM, 1);
    kQKV<<<gP, NTHR, SMEM_DYN>>>(Xr, Wc, Q, Kd, Vt, 1.0f);

    // scores = (1/32) * Q K^T per batch, causal tile skip + diag warp-skip
    dim3 gS(SEQ / BN, SEQ / BM, BATCH);
    kSco<<<gS, NTHR, SMEM_DYN>>>(Q, Kd, Sc, Sc, Sc, 0.03125f);

    softmax_causal<<<BATCH * SEQ, 256>>>(Sc, SEQ);

    // out = P V per batch : NT with B = Vt, causal K bound, LPT ordering
    dim3 gPV(DIM / BN, SEQ / BM, BATCH);
    kPV<<<gPV, NTHR, SMEM_DYN>>>(Sc, Vt, out, out, out, 1.0f);
}